// round 2
// baseline (speedup 1.0000x reference)
#include <cuda_runtime.h>
#include <cuda_bf16.h>
#include <math.h>

// Problem constants
#define BATCH   8
#define CHW     256         // C
#define HH      64
#define WW      64
#define LL      (HH*WW)     // 4096
#define NHEADS  8
#define NSAMP   4
#define DHEAD   32          // C / NHEADS
#define NPO     96          // 32 logits + 64 offsets

// ---------------- scratch (static device memory; no allocations) ------------
__device__ float g_Wpo[NPO * CHW];
__device__ float g_bpo[NPO];
__device__ float g_probj[(size_t)BATCH * LL * NPO];          // 12.6 MB
__device__ float g_vt  [(size_t)BATCH * LL * CHW];           // 33.5 MB, layout [b,l,c]
__device__ float g_agg [(size_t)BATCH * LL * CHW];           // 33.5 MB, layout [b,l,c]

// ---------------- pack w_att/w_off into one [96,256] weight ------------------
__global__ void pack_po_kernel(const float* __restrict__ w_att,
                               const float* __restrict__ b_att,
                               const float* __restrict__ w_off,
                               const float* __restrict__ b_off) {
    int idx = blockIdx.x * blockDim.x + threadIdx.x;
    if (idx < NPO * CHW) {
        int r = idx / CHW;
        int c = idx % CHW;
        g_Wpo[idx] = (r < 32) ? w_att[r * CHW + c] : w_off[(r - 32) * CHW + c];
    }
    if (idx < NPO) {
        g_bpo[idx] = (idx < 32) ? b_att[idx] : b_off[idx - 32];
    }
}

// ---------------- tiled SGEMM ------------------------------------------------
// Computes Out[m,n] = sum_k A[m,k]*W[n,k] + bias[n] per batch.
// A_KMAJOR:  A stored as [K, M] per batch (x layout [C, L])  else [M, K].
// OUT_NMAJOR: Out stored as [N, M] per batch (y layout)      else [M, N].
#define BM 64
#define BN 64
#define BKK 16

template <bool A_KMAJOR, bool OUT_NMAJOR>
__global__ __launch_bounds__(256) void sgemm_kernel(
    const float* __restrict__ A, const float* __restrict__ W,
    const float* __restrict__ bias, float* __restrict__ Out,
    int M, int N, int K, long strideA, long strideO)
{
    const int b = blockIdx.z;
    const float* Ab = A + (size_t)b * strideA;
    float* Ob = Out + (size_t)b * strideO;
    const int bm = blockIdx.x * BM;
    const int bn = blockIdx.y * BN;

    __shared__ float As[BKK][BM];   // [k][m]
    __shared__ float Bs[BKK][BN];   // [k][n]

    const int tid = threadIdx.x;
    const int tm = (tid / 16) * 4;
    const int tn = (tid % 16) * 4;

    float acc[4][4];
#pragma unroll
    for (int i = 0; i < 4; i++)
#pragma unroll
        for (int j = 0; j < 4; j++) acc[i][j] = 0.f;

    for (int k0 = 0; k0 < K; k0 += BKK) {
        // ---- load A tile ----
        if (A_KMAJOR) {
            // A[k*M + m], coalesced along m
            int r = tid / 16;            // k 0..15
            int c = (tid % 16) * 4;      // m
            float4 v = *reinterpret_cast<const float4*>(
                &Ab[(size_t)(k0 + r) * M + bm + c]);
            *reinterpret_cast<float4*>(&As[r][c]) = v;
        } else {
            // A[m*K + k], coalesced along k, store transposed
            int m = tid / 4;             // 0..63
            int c = (tid % 4) * 4;       // k
            float4 v = *reinterpret_cast<const float4*>(
                &Ab[(size_t)(bm + m) * K + k0 + c]);
            As[c + 0][m] = v.x;
            As[c + 1][m] = v.y;
            As[c + 2][m] = v.z;
            As[c + 3][m] = v.w;
        }
        // ---- load W tile: W[n*K + k] -> Bs[k][n] ----
        {
            int n = tid / 4;             // 0..63
            int c = (tid % 4) * 4;       // k
            float4 v = make_float4(0.f, 0.f, 0.f, 0.f);
            if (bn + n < N)
                v = *reinterpret_cast<const float4*>(
                    &W[(size_t)(bn + n) * K + k0 + c]);
            Bs[c + 0][n] = v.x;
            Bs[c + 1][n] = v.y;
            Bs[c + 2][n] = v.z;
            Bs[c + 3][n] = v.w;
        }
        __syncthreads();
#pragma unroll
        for (int k = 0; k < BKK; k++) {
            float4 av = *reinterpret_cast<const float4*>(&As[k][tm]);
            float4 bv = *reinterpret_cast<const float4*>(&Bs[k][tn]);
            float a[4] = {av.x, av.y, av.z, av.w};
            float bb[4] = {bv.x, bv.y, bv.z, bv.w};
#pragma unroll
            for (int i = 0; i < 4; i++)
#pragma unroll
                for (int j = 0; j < 4; j++) acc[i][j] += a[i] * bb[j];
        }
        __syncthreads();
    }

    // ---- epilogue ----
#pragma unroll
    for (int j = 0; j < 4; j++) {
        int n = bn + tn + j;
        if (n >= N) continue;
        float bvv = bias ? bias[n] : 0.f;
#pragma unroll
        for (int i = 0; i < 4; i++) {
            int m = bm + tm + i;
            float v = acc[i][j] + bvv;
            if (OUT_NMAJOR)
                Ob[(size_t)n * M + m] = v;
            else
                Ob[(size_t)m * N + n] = v;
        }
    }
}

// ---------------- deformable sampling + aggregation --------------------------
// One block per point p = b*L + l; warp = head, lane = channel-within-head.
__global__ __launch_bounds__(256) void sample_kernel()
{
    const int p = blockIdx.x;
    const int b = p >> 12;              // / 4096
    const int l = p & (LL - 1);
    const int i = l >> 6;               // row
    const int j = l & (WW - 1);         // col
    const int head = threadIdx.x >> 5;  // 0..7
    const int lane = threadIdx.x & 31;  // 0..31

    const float* pr = g_probj + (size_t)p * NPO;

    // softmax over the 4 logits of this head
    float lg[NSAMP];
#pragma unroll
    for (int n = 0; n < NSAMP; n++) lg[n] = pr[head * NSAMP + n];
    float mx = fmaxf(fmaxf(lg[0], lg[1]), fmaxf(lg[2], lg[3]));
    float e[NSAMP], s = 0.f;
#pragma unroll
    for (int n = 0; n < NSAMP; n++) { e[n] = __expf(lg[n] - mx); s += e[n]; }
    float inv = 1.f / s;

    const float ref_y = ((i + 0.5f) / (HH - 1)) * 2.f - 1.f;
    const float ref_x = ((j + 0.5f) / (WW - 1)) * 2.f - 1.f;

    const float* vtb = g_vt + (size_t)b * LL * CHW + head * DHEAD + lane;

    float acc = 0.f;
#pragma unroll
    for (int n = 0; n < NSAMP; n++) {
        float oy = pr[32 + (head * NSAMP + n) * 2 + 0];
        float ox = pr[32 + (head * NSAMP + n) * 2 + 1];
        float y = (ref_y + oy + 1.f) * 0.5f * (HH - 1);
        float x = (ref_x + ox + 1.f) * 0.5f * (WW - 1);
        float y0 = floorf(y);
        float x0 = floorf(x);
        float sv = 0.f;
#pragma unroll
        for (int dy = 0; dy < 2; dy++) {
#pragma unroll
            for (int dx = 0; dx < 2; dx++) {
                float yi = y0 + dy;
                float xi = x0 + dx;
                float w = (1.f - fabsf(y - yi)) * (1.f - fabsf(x - xi));
                bool valid = (yi >= 0.f) && (yi < HH) && (xi >= 0.f) && (xi < WW);
                int yc = min(max((int)yi, 0), HH - 1);
                int xc = min(max((int)xi, 0), WW - 1);
                int idx = yc * WW + xc;
                float val = vtb[(size_t)idx * CHW];
                if (valid) sv += w * val;
            }
        }
        acc += (e[n] * inv) * sv;
    }
    g_agg[(size_t)b * LL * CHW + (size_t)l * CHW + head * DHEAD + lane] = acc;
}

// ---------------- launch ------------------------------------------------------
extern "C" void kernel_launch(void* const* d_in, const int* in_sizes, int n_in,
                              void* d_out, int out_size)
{
    const float* x     = (const float*)d_in[0];  // [B, C, H, W]
    const float* w_att = (const float*)d_in[1];  // [32, C]
    const float* b_att = (const float*)d_in[2];  // [32]
    const float* w_off = (const float*)d_in[3];  // [64, C]
    const float* b_off = (const float*)d_in[4];  // [64]
    const float* w_v   = (const float*)d_in[5];  // [C, C]
    const float* b_v   = (const float*)d_in[6];  // [C]
    const float* w_out = (const float*)d_in[7];  // [C, C]
    const float* b_out = (const float*)d_in[8];  // [C]
    float* y = (float*)d_out;                    // [B, C, H, W]

    void *pWpo, *pbpo, *pprobj, *pvt, *pagg;
    cudaGetSymbolAddress(&pWpo, g_Wpo);
    cudaGetSymbolAddress(&pbpo, g_bpo);
    cudaGetSymbolAddress(&pprobj, g_probj);
    cudaGetSymbolAddress(&pvt, g_vt);
    cudaGetSymbolAddress(&pagg, g_agg);

    // 1. pack logits/offset projection weights
    pack_po_kernel<<<(NPO * CHW + 255) / 256, 256>>>(w_att, b_att, w_off, b_off);

    // 2. probj = x^T @ Wpo^T + bpo   (A K-major: x is [C, L] per batch)
    {
        dim3 grid(LL / BM, (NPO + BN - 1) / BN, BATCH);
        sgemm_kernel<true, false><<<grid, 256>>>(
            x, (const float*)pWpo, (const float*)pbpo, (float*)pprobj,
            LL, NPO, CHW, (long)CHW * LL, (long)LL * NPO);
    }

    // 3. v_t = x^T @ w_v^T + b_v  -> [b, l, c]
    {
        dim3 grid(LL / BM, CHW / BN, BATCH);
        sgemm_kernel<true, false><<<grid, 256>>>(
            x, w_v, b_v, (float*)pvt,
            LL, CHW, CHW, (long)CHW * LL, (long)LL * CHW);
    }

    // 4. deformable bilinear sampling + softmax aggregation -> agg [b, l, c]
    sample_kernel<<<BATCH * LL, 256>>>();

    // 5. y = agg @ w_out^T + b_out, output layout [b, o, l] (N-major)
    {
        dim3 grid(LL / BM, CHW / BN, BATCH);
        sgemm_kernel<false, true><<<grid, 256>>>(
            (const float*)pagg, w_out, b_out, y,
            LL, CHW, CHW, (long)LL * CHW, (long)CHW * LL);
    }
}

// round 17
// speedup vs baseline: 1.3020x; 1.3020x over previous
#include <cuda_runtime.h>
#include <cuda_bf16.h>
#include <math.h>
#include <stdint.h>

// ---------------- problem constants ----------------
#define BATCH   8
#define CHW     256
#define HH      64
#define WW      64
#define LLEN    4096
#define NHEADS  8
#define NSAMP   4
#define NPO     96

// ---------------- static device scratch ----------------
__device__ __nv_bfloat16 g_xt_hi[(size_t)BATCH * LLEN * CHW];   // [b,l,c] bf16
__device__ __nv_bfloat16 g_xt_lo[(size_t)BATCH * LLEN * CHW];
__device__ __nv_bfloat16 g_agg_hi[(size_t)BATCH * LLEN * CHW];  // [b,l,c]
__device__ __nv_bfloat16 g_agg_lo[(size_t)BATCH * LLEN * CHW];
__device__ __nv_bfloat16 g_wv_hi[CHW * CHW], g_wv_lo[CHW * CHW];
__device__ __nv_bfloat16 g_wo_hi[CHW * CHW], g_wo_lo[CHW * CHW];
__device__ __nv_bfloat16 g_wpo_hi[NPO * CHW], g_wpo_lo[NPO * CHW];
__device__ float g_vt[(size_t)BATCH * LLEN * CHW];              // [b,l,c] fp32
__device__ float g_probj[(size_t)BATCH * LLEN * NPO];           // [p,96]

// ---------------- helpers ----------------
__device__ __forceinline__ uint32_t smem_u32(const void* p) {
    uint32_t a;
    asm("{ .reg .u64 t; cvta.to.shared.u64 t, %1; cvt.u32.u64 %0, t; }"
        : "=r"(a) : "l"(p));
    return a;
}
__device__ __forceinline__ void ldsm_x4(uint32_t* rr, uint32_t addr) {
    asm volatile("ldmatrix.sync.aligned.m8n8.x4.shared.b16 {%0,%1,%2,%3}, [%4];"
        : "=r"(rr[0]), "=r"(rr[1]), "=r"(rr[2]), "=r"(rr[3]) : "r"(addr));
}
__device__ __forceinline__ void mma_16816(float* d, const uint32_t* a,
                                          const uint32_t* b) {
    asm volatile(
        "mma.sync.aligned.m16n8k16.row.col.f32.bf16.bf16.f32 "
        "{%0,%1,%2,%3}, {%4,%5,%6,%7}, {%8,%9}, {%0,%1,%2,%3};\n"
        : "+f"(d[0]), "+f"(d[1]), "+f"(d[2]), "+f"(d[3])
        : "r"(a[0]), "r"(a[1]), "r"(a[2]), "r"(a[3]), "r"(b[0]), "r"(b[1]));
}
__device__ __forceinline__ void split2(float v, __nv_bfloat16& h, __nv_bfloat16& l) {
    h = __float2bfloat16(v);
    l = __float2bfloat16(v - __bfloat162float(h));
}

// ---------------- conversion kernels ----------------
__global__ __launch_bounds__(256) void convert_x_kernel(const float* __restrict__ x) {
    __shared__ float t[32][33];
    const int b = blockIdx.z, l0 = blockIdx.x * 32, c0 = blockIdx.y * 32;
    const int tx = threadIdx.x, ty = threadIdx.y;
#pragma unroll
    for (int r = 0; r < 4; r++) {
        int c = c0 + ty + r * 8;
        t[ty + r * 8][tx] = x[((size_t)(b * CHW + c)) * LLEN + l0 + tx];
    }
    __syncthreads();
#pragma unroll
    for (int r = 0; r < 4; r++) {
        int l = l0 + ty + r * 8;
        float v = t[tx][ty + r * 8];
        __nv_bfloat16 h, lo;
        split2(v, h, lo);
        size_t o = ((size_t)(b * LLEN + l)) * CHW + c0 + tx;
        g_xt_hi[o] = h;
        g_xt_lo[o] = lo;
    }
}

__global__ __launch_bounds__(256) void prep_weights_kernel(
    const float* __restrict__ w_att, const float* __restrict__ w_off,
    const float* __restrict__ w_v, const float* __restrict__ w_out) {
    int idx = blockIdx.x * blockDim.x + threadIdx.x;
    const int S1 = CHW * CHW, S2 = 2 * CHW * CHW, S3 = 2 * CHW * CHW + NPO * CHW;
    if (idx >= S3) return;
    __nv_bfloat16 h, l;
    if (idx < S1) {
        split2(w_v[idx], h, l);
        g_wv_hi[idx] = h; g_wv_lo[idx] = l;
    } else if (idx < S2) {
        int j = idx - S1;
        split2(w_out[j], h, l);
        g_wo_hi[j] = h; g_wo_lo[j] = l;
    } else {
        int j = idx - S2;
        float v = (j < 32 * CHW) ? w_att[j] : w_off[j - 32 * CHW];
        split2(v, h, l);
        g_wpo_hi[j] = h; g_wpo_lo[j] = l;
    }
}

// ---------------- HMMA (mma.sync) GEMM ----------------
// D[m,n] = sum_k A[m,k]*B[n,k] + bias; A,B bf16 hi/lo split, 3 passes, fp32 acc.
// CTA tile: M=128, N=TILE_N, K=256 fully smem-resident.
// smem rows are 512B (256 bf16) with 16B-chunk XOR swizzle: chunk' = chunk ^ (row&7).
// MODE 0: out fp32 [b,l,c].  MODE 1: probj [p,96], bias att/off.  MODE 2: y [b,c,l].
template <int TILE_N, int MODE>
__global__ __launch_bounds__(256) void hmma_gemm_kernel(
    const __nv_bfloat16* __restrict__ A_hi, const __nv_bfloat16* __restrict__ A_lo,
    const __nv_bfloat16* __restrict__ B_hi, const __nv_bfloat16* __restrict__ B_lo,
    float* __restrict__ out, const float* __restrict__ bias_a,
    const float* __restrict__ bias_b, int n_base)
{
    extern __shared__ char smem[];
    constexpr int SA_HI = 0;
    constexpr int SA_LO = 128 * 512;            // 65536
    constexpr int SB_HI = 2 * 128 * 512;        // 131072
    constexpr int SB_LO = SB_HI + TILE_N * 512;
    constexpr int WN = TILE_N / 32;             // warps along n (2 or 1)
    constexpr int WM = 8 / WN;                  // warps along m (4 or 8)
    constexpr int MT = 128 / (WM * 16);         // m16 tiles per warp (2 or 1)

    const int tid = threadIdx.x;
    const int wid = tid >> 5;
    const int lane = tid & 31;
    const int bm = blockIdx.x * 128;
    const int n0 = n_base + blockIdx.y * TILE_N;
    const int bb = blockIdx.z;

    const __nv_bfloat16* Ah = A_hi + (size_t)bb * LLEN * CHW;
    const __nv_bfloat16* Al = A_lo + (size_t)bb * LLEN * CHW;

    // ---- fill A hi/lo: 128 rows x 32 chunks(16B) each, swizzled
    for (int g = tid; g < 8192; g += 256) {
        int buf = g >> 12, gg = g & 4095;
        int m = gg >> 5, c = gg & 31;
        uint4 v = *reinterpret_cast<const uint4*>(
            (buf ? Al : Ah) + (size_t)(bm + m) * 256 + c * 8);
        *reinterpret_cast<uint4*>(
            smem + (buf ? SA_LO : SA_HI) + m * 512 + ((c ^ (m & 7)) << 4)) = v;
    }
    // ---- fill B hi/lo: TILE_N rows x 32 chunks
    for (int g = tid; g < 2 * TILE_N * 32; g += 256) {
        int buf = (g >= TILE_N * 32);
        int gg = buf ? g - TILE_N * 32 : g;
        int n = gg >> 5, c = gg & 31;
        uint4 v = *reinterpret_cast<const uint4*>(
            (buf ? B_lo : B_hi) + (size_t)(n0 + n) * 256 + c * 8);
        *reinterpret_cast<uint4*>(
            smem + (buf ? SB_LO : SB_HI) + n * 512 + ((c ^ (n & 7)) << 4)) = v;
    }
    __syncthreads();

    const uint32_t smem_u = smem_u32(smem);
    const int wm = wid / WN, wn = wid % WN;
    const int mbase = wm * (MT * 16);
    const int nbase = wn * 32;                  // each warp covers 32 n (4 n8-tiles)

    const int q = lane >> 3, r = lane & 7;
    const int qh = q >> 1, ql = q & 1;

    // A ldmatrix.x4 matrix order: (m0-7,c0),(m8-15,c0),(m0-7,c1),(m8-15,c1)
    uint32_t a_rowoff[MT]; int a_rm7[MT];
#pragma unroll
    for (int mt = 0; mt < MT; mt++) {
        int row = mbase + mt * 16 + ql * 8 + r;
        a_rowoff[mt] = row * 512;
        a_rm7[mt] = row & 7;
    }
    // B ldmatrix.x4 #0: matrices (n0-7,c0),(n0-7,c1),(n8-15,c0),(n8-15,c1)
    //               #1: same for n16-31
    int brow0 = nbase + qh * 8 + r;
    int brow1 = brow0 + 16;
    uint32_t b_rowoff0 = brow0 * 512; int b_rm70 = brow0 & 7;
    uint32_t b_rowoff1 = brow1 * 512; int b_rm71 = brow1 & 7;

    float acc[MT][4][4];
#pragma unroll
    for (int mt = 0; mt < MT; mt++)
#pragma unroll
        for (int nt = 0; nt < 4; nt++)
#pragma unroll
            for (int i = 0; i < 4; i++) acc[mt][nt][i] = 0.f;

    // ---- 3 split passes (hi*hi, lo*hi, hi*lo) x 16 k16-steps
#pragma unroll
    for (int pass = 0; pass < 3; pass++) {
        uint32_t Ab = smem_u + ((pass == 1) ? SA_LO : SA_HI);
        uint32_t Bb = smem_u + ((pass == 2) ? SB_LO : SB_HI);
#pragma unroll
        for (int kk = 0; kk < 16; kk++) {
            uint32_t af[MT][4];
            int ca = kk * 2 + qh;
#pragma unroll
            for (int mt = 0; mt < MT; mt++)
                ldsm_x4(af[mt], Ab + a_rowoff[mt] + ((ca ^ a_rm7[mt]) << 4));
            int cb = kk * 2 + ql;
            uint32_t t0[4], t1[4];
            ldsm_x4(t0, Bb + b_rowoff0 + ((cb ^ b_rm70) << 4));
            ldsm_x4(t1, Bb + b_rowoff1 + ((cb ^ b_rm71) << 4));
            uint32_t bf[4][2] = {{t0[0], t0[1]}, {t0[2], t0[3]},
                                 {t1[0], t1[1]}, {t1[2], t1[3]}};
#pragma unroll
            for (int mt = 0; mt < MT; mt++)
#pragma unroll
                for (int nt = 0; nt < 4; nt++)
                    mma_16816(acc[mt][nt], af[mt], bf[nt]);
        }
    }
    __syncthreads();

    // ---- stage fragments to smem (reuse A region), then coalesced global write
    constexpr int PS = 66;  // padded row stride (floats), even for float2 alignment
    float* stage = reinterpret_cast<float*>(smem);
    const int sm_r = lane >> 2;
    const int sn = (lane & 3) * 2;
#pragma unroll
    for (int mt = 0; mt < MT; mt++) {
        int m = mbase + mt * 16 + sm_r;
#pragma unroll
        for (int nt = 0; nt < 4; nt++) {
            int n = nbase + nt * 8 + sn;
            *reinterpret_cast<float2*>(&stage[m * PS + n]) =
                make_float2(acc[mt][nt][0], acc[mt][nt][1]);
            *reinterpret_cast<float2*>(&stage[(m + 8) * PS + n]) =
                make_float2(acc[mt][nt][2], acc[mt][nt][3]);
        }
    }
    __syncthreads();

    if (MODE == 2) {
        float* ob = out + (size_t)bb * CHW * LLEN + bm;
        for (int g = tid; g < TILE_N * 128; g += 256) {
            int c = g >> 7, m = g & 127;
            ob[(size_t)(n0 + c) * LLEN + m] = stage[m * PS + c] + bias_a[n0 + c];
        }
    } else {
        const int ostr = (MODE == 1) ? NPO : CHW;
        float* ob = out + (size_t)bb * LLEN * ostr;
        for (int g = tid; g < 128 * TILE_N; g += 256) {
            int m = g / TILE_N, c = g - m * TILE_N;
            int gn = n0 + c;
            float bv = (MODE == 1) ? ((gn < 32) ? bias_a[gn] : bias_b[gn - 32])
                                   : bias_a[gn];
            ob[(size_t)(bm + m) * ostr + gn] = stage[m * PS + c] + bv;
        }
    }
}

// ---------------- deformable sampling + aggregation ----------------
__global__ __launch_bounds__(256) void sample_kernel()
{
    const int p = blockIdx.x;
    const int b = p >> 12;
    const int l = p & (LLEN - 1);
    const int i = l >> 6;
    const int j = l & (WW - 1);
    const int head = threadIdx.x >> 5;
    const int lane = threadIdx.x & 31;

    const float* __restrict__ pr = g_probj + (size_t)p * NPO;

    float lg0 = pr[head * 4 + 0], lg1 = pr[head * 4 + 1];
    float lg2 = pr[head * 4 + 2], lg3 = pr[head * 4 + 3];
    float mx = fmaxf(fmaxf(lg0, lg1), fmaxf(lg2, lg3));
    float e0 = __expf(lg0 - mx), e1 = __expf(lg1 - mx);
    float e2 = __expf(lg2 - mx), e3 = __expf(lg3 - mx);
    float inv = 1.f / (e0 + e1 + e2 + e3);
    float an[NSAMP] = {e0 * inv, e1 * inv, e2 * inv, e3 * inv};

    const float ref_y = ((i + 0.5f) * (1.f / 63.f)) * 2.f - 1.f;
    const float ref_x = ((j + 0.5f) * (1.f / 63.f)) * 2.f - 1.f;

    const float* __restrict__ base = g_vt + ((size_t)b << 20) + (head << 5) + lane;

    float acc = 0.f;
#pragma unroll
    for (int n = 0; n < NSAMP; n++) {
        float oy = pr[32 + (head * 4 + n) * 2 + 0];
        float ox = pr[32 + (head * 4 + n) * 2 + 1];
        float y = (ref_y + oy + 1.f) * 0.5f * 63.f;
        float x = (ref_x + ox + 1.f) * 0.5f * 63.f;
        float y0f = floorf(y), x0f = floorf(x);
        float fy = y - y0f, fx = x - x0f;
        int y0 = (int)y0f, x0 = (int)x0f;
        float wy0 = 1.f - fy, wy1 = fy;
        float wx0 = 1.f - fx, wx1 = fx;
        if ((unsigned)y0 > 63u) wy0 = 0.f;
        if ((unsigned)(y0 + 1) > 63u) wy1 = 0.f;
        if ((unsigned)x0 > 63u) wx0 = 0.f;
        if ((unsigned)(x0 + 1) > 63u) wx1 = 0.f;
        int y0c = min(max(y0, 0), 63), y1c = min(max(y0 + 1, 0), 63);
        int x0c = min(max(x0, 0), 63), x1c = min(max(x0 + 1, 0), 63);
        int r0 = y0c << 6, r1 = y1c << 6;
        float v00 = __ldg(base + ((r0 + x0c) << 8));
        float v01 = __ldg(base + ((r0 + x1c) << 8));
        float v10 = __ldg(base + ((r1 + x0c) << 8));
        float v11 = __ldg(base + ((r1 + x1c) << 8));
        float sv = wy0 * (wx0 * v00 + wx1 * v01) + wy1 * (wx0 * v10 + wx1 * v11);
        acc = fmaf(an[n], sv, acc);
    }

    __nv_bfloat16 h, lo;
    split2(acc, h, lo);
    size_t o = ((size_t)p << 8) + (head << 5) + lane;
    g_agg_hi[o] = h;
    g_agg_lo[o] = lo;
}

// ---------------- launch ----------------
extern "C" void kernel_launch(void* const* d_in, const int* in_sizes, int n_in,
                              void* d_out, int out_size)
{
    const float* x     = (const float*)d_in[0];
    const float* w_att = (const float*)d_in[1];
    const float* b_att = (const float*)d_in[2];
    const float* w_off = (const float*)d_in[3];
    const float* b_off = (const float*)d_in[4];
    const float* w_v   = (const float*)d_in[5];
    const float* b_v   = (const float*)d_in[6];
    const float* w_out = (const float*)d_in[7];
    const float* b_out = (const float*)d_in[8];
    float* y = (float*)d_out;

    void *pxh, *pxl, *pah, *pal, *pvh, *pvl, *poh, *pol, *pph, *ppl, *pvt, *ppr;
    cudaGetSymbolAddress(&pxh, g_xt_hi);
    cudaGetSymbolAddress(&pxl, g_xt_lo);
    cudaGetSymbolAddress(&pah, g_agg_hi);
    cudaGetSymbolAddress(&pal, g_agg_lo);
    cudaGetSymbolAddress(&pvh, g_wv_hi);
    cudaGetSymbolAddress(&pvl, g_wv_lo);
    cudaGetSymbolAddress(&poh, g_wo_hi);
    cudaGetSymbolAddress(&pol, g_wo_lo);
    cudaGetSymbolAddress(&pph, g_wpo_hi);
    cudaGetSymbolAddress(&ppl, g_wpo_lo);
    cudaGetSymbolAddress(&pvt, g_vt);
    cudaGetSymbolAddress(&ppr, g_probj);

    const int SM64 = 2 * 128 * 512 + 2 * 64 * 512;   // 196,608
    const int SM32 = 2 * 128 * 512 + 2 * 32 * 512;   // 163,840
    cudaFuncSetAttribute(hmma_gemm_kernel<64, 0>, cudaFuncAttributeMaxDynamicSharedMemorySize, SM64);
    cudaFuncSetAttribute(hmma_gemm_kernel<64, 1>, cudaFuncAttributeMaxDynamicSharedMemorySize, SM64);
    cudaFuncSetAttribute(hmma_gemm_kernel<32, 1>, cudaFuncAttributeMaxDynamicSharedMemorySize, SM32);
    cudaFuncSetAttribute(hmma_gemm_kernel<64, 2>, cudaFuncAttributeMaxDynamicSharedMemorySize, SM64);

    // 1. convert x -> [b,l,c] bf16 hi/lo
    convert_x_kernel<<<dim3(LLEN / 32, CHW / 32, BATCH), dim3(32, 8)>>>(x);
    // 2. weight splits
    prep_weights_kernel<<<(2 * CHW * CHW + NPO * CHW + 255) / 256, 256>>>(
        w_att, w_off, w_v, w_out);

    // 3. probj = xt @ Wpo^T + bias  (N=96 as 64 + 32 tiles)
    hmma_gemm_kernel<64, 1><<<dim3(32, 1, BATCH), 256, SM64>>>(
        (const __nv_bfloat16*)pxh, (const __nv_bfloat16*)pxl,
        (const __nv_bfloat16*)pph, (const __nv_bfloat16*)ppl,
        (float*)ppr, b_att, b_off, 0);
    hmma_gemm_kernel<32, 1><<<dim3(32, 1, BATCH), 256, SM32>>>(
        (const __nv_bfloat16*)pxh, (const __nv_bfloat16*)pxl,
        (const __nv_bfloat16*)pph, (const __nv_bfloat16*)ppl,
        (float*)ppr, b_att, b_off, 64);

    // 4. v = xt @ w_v^T + b_v -> g_vt [b,l,c]
    hmma_gemm_kernel<64, 0><<<dim3(32, 4, BATCH), 256, SM64>>>(
        (const __nv_bfloat16*)pxh, (const __nv_bfloat16*)pxl,
        (const __nv_bfloat16*)pvh, (const __nv_bfloat16*)pvl,
        (float*)pvt, b_v, nullptr, 0);

    // 5. deformable sampling -> agg hi/lo bf16 [b,l,c]
    sample_kernel<<<BATCH * LLEN, 256>>>();

    // 6. y = agg @ w_out^T + b_out, written [b,c,l]
    hmma_gemm_kernel<64, 2><<<dim3(32, 4, BATCH), 256, SM64>>>(
        (const __nv_bfloat16*)pah, (const __nv_bfloat16*)pal,
        (const __nv_bfloat16*)poh, (const __nv_bfloat16*)pol,
        y, b_out, nullptr, 0);
}